// round 10
// baseline (speedup 1.0000x reference)
#include <cuda_runtime.h>
#include <cuda_bf16.h>
#include <math.h>
#include <stddef.h>
#include <stdint.h>

#define D 512
#define LSEQ 1024
#define BATCH 8
#define NH 8
#define HD 64
#define ROWS (BATCH*LSEQ)   /* 8192 */
#define BH (BATCH*NH)       /* 64   */
#define DD (D*D)

// ---------------- scratch (no allocations allowed) ----------------
__device__ __nv_bfloat16 g_x1b[ROWS*D];
__device__ __nv_bfloat16 g_x2b[ROWS*D];
__device__ __nv_bfloat16 g_qb[(size_t)2*ROWS*D];   // [0]: mha1 Q, [1]: mha2 Q
__device__ __nv_bfloat16 g_kvb[(size_t)ROWS*2*D];
__device__ __nv_bfloat16 g_ctxb[ROWS*D];
__device__ __nv_bfloat16 g_hidb[(size_t)2*ROWS*2*D];
__device__ __nv_bfloat16 g_xlnb[(size_t)2*ROWS*D];
__device__ __nv_bfloat16 g_wb[(size_t)12*DD];
__device__ float g_proj[ROWS*D];
__device__ float g_ffn[(size_t)2*ROWS*D];

// weight offsets in g_wb (ORDER MATCHES convert_all layout)
#define WB_W1  0           /* win1: 3DD */
#define WB_WO1 (3*DD)      /* wout1: DD */
#define WB_W2  (4*DD)      /* win2: 3DD */
#define WB_WO2 (7*DD)      /* wout2: DD */
#define WB_F1  (8*DD)      /* fw1: 2DD  */
#define WB_F2  (10*DD)     /* fw2: 2DD  */

// ======================= helpers =======================
__device__ __forceinline__ uint32_t smem_u32(const void* p) {
  uint32_t a;
  asm("{ .reg .u64 t; cvta.to.shared.u64 t, %1; cvt.u32.u64 %0, t; }"
      : "=r"(a) : "l"(p));
  return a;
}

#define CP_ASYNC16(dst, src) \
  asm volatile("cp.async.cg.shared.global [%0], [%1], 16;" \
               :: "r"(dst), "l"(src))
#define CP_COMMIT() asm volatile("cp.async.commit_group;")
#define CP_WAIT(n)  asm volatile("cp.async.wait_group %0;" :: "n"(n))

#define LDSM_X4(r0, r1, r2, r3, addr) \
  asm volatile("ldmatrix.sync.aligned.m8n8.x4.shared.b16 {%0,%1,%2,%3}, [%4];" \
               : "=r"(r0), "=r"(r1), "=r"(r2), "=r"(r3) : "r"(addr))
#define LDSM_X4_T(r0, r1, r2, r3, addr) \
  asm volatile("ldmatrix.sync.aligned.m8n8.x4.trans.shared.b16 {%0,%1,%2,%3}, [%4];" \
               : "=r"(r0), "=r"(r1), "=r"(r2), "=r"(r3) : "r"(addr))

#define MMA_BF16(c, a, b) \
  asm volatile( \
    "mma.sync.aligned.m16n8k16.row.col.f32.bf16.bf16.f32 " \
    "{%0,%1,%2,%3}, {%4,%5,%6,%7}, {%8,%9}, {%0,%1,%2,%3};" \
    : "+f"((c)[0]), "+f"((c)[1]), "+f"((c)[2]), "+f"((c)[3]) \
    : "r"((a)[0]), "r"((a)[1]), "r"((a)[2]), "r"((a)[3]), \
      "r"((b)[0]), "r"((b)[1]))

// ---------------- all fp32 -> bf16 converts in ONE launch -----------------
#define CV_Q4   (ROWS*D/4)
#define CV_C3   (3*DD/4)
#define CV_C1   (DD/4)
#define CV_C2   (2*DD/4)
#define CV_WTOT (12*DD/4)
#define CV_TOT  (2*CV_Q4 + CV_WTOT)
#define CV_BLOCKS (CV_TOT/256)

__global__ void __launch_bounds__(256) convert_all(
    const float* __restrict__ x1, const float* __restrict__ x2,
    const float* __restrict__ win1, const float* __restrict__ wout1,
    const float* __restrict__ win2, const float* __restrict__ wout2,
    const float* __restrict__ fw1, const float* __restrict__ fw2,
    __nv_bfloat16* __restrict__ x1b, __nv_bfloat16* __restrict__ x2b,
    __nv_bfloat16* __restrict__ wb)
{
  long i = (long)blockIdx.x * 256 + threadIdx.x;
  const float* src;
  __nv_bfloat16* dstb;
  long off, sidx;
  if (i < CV_Q4) { src = x1; dstb = x1b; off = i; sidx = i; }
  else if (i < 2 * CV_Q4) { src = x2; dstb = x2b; off = i - CV_Q4; sidx = off; }
  else {
    long w = i - 2 * CV_Q4;
    dstb = wb; sidx = w;
    if      (w < CV_C3)                 { src = win1;  off = w; }
    else if (w < CV_C3 + CV_C1)         { src = wout1; off = w - CV_C3; }
    else if (w < 2*CV_C3 + CV_C1)       { src = win2;  off = w - (CV_C3 + CV_C1); }
    else if (w < 2*CV_C3 + 2*CV_C1)     { src = wout2; off = w - (2*CV_C3 + CV_C1); }
    else if (w < 2*CV_C3 + 2*CV_C1 + CV_C2) { src = fw1; off = w - (2*CV_C3 + 2*CV_C1); }
    else                                { src = fw2;  off = w - (2*CV_C3 + 2*CV_C1 + CV_C2); }
  }
  float4 v = ((const float4*)src)[off];
  __nv_bfloat162 a = __floats2bfloat162_rn(v.x, v.y);
  __nv_bfloat162 b = __floats2bfloat162_rn(v.z, v.w);
  ((uint2*)dstb)[sidx] = make_uint2(*(uint32_t*)&a, *(uint32_t*)&b);
}

// ======================= bf16 GEMM device core =============================
// C = A[M,K] @ B[N,K]^T + bias; 256x128 CTA tile, 64x64 warp tile, K-slab 32,
// 3-stage cp.async. Tile indices (bx, by) passed in for merged-launch routing.
#define GE_ASTAGE (256*80)
#define GE_BSTAGE (128*80)
#define GE_STAGE  (GE_ASTAGE+GE_BSTAGE)
#define GE_SMEM   (3*GE_STAGE)             /* 92160 */

__device__ __forceinline__ void gemm_dev(
    const __nv_bfloat16* __restrict__ A, const __nv_bfloat16* __restrict__ B,
    const float* __restrict__ bias, float* __restrict__ Cf,
    __nv_bfloat16* __restrict__ Cb,
    int nslab, int lda, int ldb, int ldc, int relu,
    int bx, int by, char* gsm)
{
  const uint32_t asb = smem_u32(gsm);

  const int tid = threadIdx.x;
  const int wid = tid >> 5, l = tid & 31;
  const int warp_m = wid & 3, warp_n = wid >> 2;

  const int bm = by * 256;
  const int bn = bx * 128;

  float acc[4][8][4];
  #pragma unroll
  for (int i = 0; i < 4; i++)
    #pragma unroll
    for (int j = 0; j < 8; j++)
      #pragma unroll
      for (int k = 0; k < 4; k++) acc[i][j][k] = 0.f;

  auto issue = [&](int slab, int stg) {
    const int k0 = slab << 5;
    const uint32_t ab = asb + stg * GE_STAGE;
    const uint32_t bb = ab + GE_ASTAGE;
    #pragma unroll
    for (int it = 0; it < 4; ++it) {
      int idx = tid + it * 256;
      int r = idx >> 2, c = (idx & 3) << 3;
      CP_ASYNC16(ab + (uint32_t)(r * 80 + c * 2),
                 A + (size_t)(bm + r) * lda + k0 + c);
    }
    #pragma unroll
    for (int it = 0; it < 2; ++it) {
      int idx = tid + it * 256;
      int r = idx >> 2, c = (idx & 3) << 3;
      CP_ASYNC16(bb + (uint32_t)(r * 80 + c * 2),
                 B + (size_t)(bn + r) * ldb + k0 + c);
    }
    CP_COMMIT();
  };

  issue(0, 0);
  if (nslab > 1) issue(1, 1); else CP_COMMIT();

  int stg = 0;
  for (int i = 0; i < nslab; i++) {
    CP_WAIT(1);
    __syncthreads();
    const int buf = stg;
    stg = (stg == 2) ? 0 : stg + 1;
    if (i + 2 < nslab) issue(i + 2, (buf + 2) % 3); else CP_COMMIT();

    const uint32_t a_base = asb + buf * GE_STAGE;
    const uint32_t b_base = a_base + GE_ASTAGE;
    #pragma unroll
    for (int ks = 0; ks < 2; ks++) {
      const int k0 = ks * 16;
      uint32_t afr[4][4];
      #pragma unroll
      for (int mf = 0; mf < 4; mf++) {
        int row = warp_m * 64 + mf * 16 + (l & 15);
        uint32_t addr = a_base + (uint32_t)(row * 80 + (k0 + ((l >> 4) << 3)) * 2);
        LDSM_X4(afr[mf][0], afr[mf][1], afr[mf][2], afr[mf][3], addr);
      }
      uint32_t bfr[8][2];
      #pragma unroll
      for (int nf = 0; nf < 8; nf += 2) {
        int row = warp_n * 64 + nf * 8 + ((l >> 4) << 3) + (l & 7);
        int col = k0 + ((l >> 3) & 1) * 8;
        uint32_t addr = b_base + (uint32_t)(row * 80 + col * 2);
        LDSM_X4(bfr[nf][0], bfr[nf][1], bfr[nf + 1][0], bfr[nf + 1][1], addr);
      }
      #pragma unroll
      for (int mf = 0; mf < 4; mf++)
        #pragma unroll
        for (int nf = 0; nf < 8; nf++)
          MMA_BF16(acc[mf][nf], afr[mf], bfr[nf]);
    }
  }

  const int gid = l >> 2, tig = l & 3;
  #pragma unroll
  for (int mf = 0; mf < 4; mf++) {
    const int row = bm + warp_m * 64 + mf * 16 + gid;
    #pragma unroll
    for (int nf = 0; nf < 8; nf++) {
      const int col = bn + warp_n * 64 + nf * 8 + tig * 2;
      float2 bv = make_float2(0.f, 0.f);
      if (bias) bv = *(const float2*)(bias + col);
      float2 v0, v1;
      v0.x = acc[mf][nf][0] + bv.x;
      v0.y = acc[mf][nf][1] + bv.y;
      v1.x = acc[mf][nf][2] + bv.x;
      v1.y = acc[mf][nf][3] + bv.y;
      if (relu) {
        v0.x = fmaxf(v0.x, 0.f); v0.y = fmaxf(v0.y, 0.f);
        v1.x = fmaxf(v1.x, 0.f); v1.y = fmaxf(v1.y, 0.f);
      }
      if (Cf) {
        *(float2*)(Cf + (size_t)row * ldc + col) = v0;
        *(float2*)(Cf + (size_t)(row + 8) * ldc + col) = v1;
      }
      if (Cb) {
        __nv_bfloat162 h0 = __floats2bfloat162_rn(v0.x, v0.y);
        __nv_bfloat162 h1 = __floats2bfloat162_rn(v1.x, v1.y);
        *(uint32_t*)(Cb + (size_t)row * ldc + col) = *(uint32_t*)&h0;
        *(uint32_t*)(Cb + (size_t)(row + 8) * ldc + col) = *(uint32_t*)&h1;
      }
    }
  }
}

// ---- plain single-job GEMM kernel ----
__global__ void __launch_bounds__(256) gemm_k(
    const __nv_bfloat16* __restrict__ A, const __nv_bfloat16* __restrict__ B,
    const float* __restrict__ bias, float* __restrict__ Cf,
    __nv_bfloat16* __restrict__ Cb,
    int nslab, int lda, int ldb, int ldc, int relu)
{
  extern __shared__ char gsm[];
  gemm_dev(A, B, bias, Cf, Cb, nslab, lda, ldb, ldc, relu,
           blockIdx.x, blockIdx.y, gsm);
}

// ---- merged: Q1 | KV1 | Q2 projections (all from converted inputs) ----
__global__ void __launch_bounds__(256) mega_qkv(
    const __nv_bfloat16* __restrict__ x1b, const __nv_bfloat16* __restrict__ x2b,
    const __nv_bfloat16* __restrict__ wb,
    const float* __restrict__ bin1, const float* __restrict__ bin2,
    __nv_bfloat16* __restrict__ qb, __nv_bfloat16* __restrict__ qb2,
    __nv_bfloat16* __restrict__ kvb)
{
  extern __shared__ char gsm[];
  const int bx = blockIdx.x, by = blockIdx.y;
  if (bx < 4) {         // Q1: x1b @ W1q  -> qb [8192,512]
    gemm_dev(x1b, wb + WB_W1, bin1, nullptr, qb, 16, D, D, D, 0, bx, by, gsm);
  } else if (bx < 12) { // KV1: x2b @ W1kv -> kvb [8192,1024]
    gemm_dev(x2b, wb + WB_W1 + DD, bin1 + D, nullptr, kvb, 16, D, D, 2*D, 0,
             bx - 4, by, gsm);
  } else {              // Q2: x2b @ W2q  -> qb2 [8192,512]
    gemm_dev(x2b, wb + WB_W2, bin2, nullptr, qb2, 16, D, D, D, 0,
             bx - 12, by, gsm);
  }
}

// ---- merged: KV2 projection | FFN1a (x1 half) — both ready after LN1 ----
__global__ void __launch_bounds__(256) mega_kv2_ffn1a(
    const __nv_bfloat16* __restrict__ xlnb1, const __nv_bfloat16* __restrict__ wb,
    const float* __restrict__ bin2, const float* __restrict__ fb1,
    __nv_bfloat16* __restrict__ kvb, __nv_bfloat16* __restrict__ hidb1)
{
  extern __shared__ char gsm[];
  const int bx = blockIdx.x, by = blockIdx.y;
  if (bx < 8) {        // KV2: xlnb1 @ W2kv -> kvb [8192,1024]
    gemm_dev(xlnb1, wb + WB_W2 + DD, bin2 + D, nullptr, kvb, 16, D, D, 2*D, 0,
             bx, by, gsm);
  } else {             // FFN1a: relu(xlnb1 @ fw1) -> hidb1 [8192,1024]
    gemm_dev(xlnb1, wb + WB_F1, fb1, nullptr, hidb1, 16, D, D, 2*D, 1,
             bx - 8, by, gsm);
  }
}

// ---- merged: out2 projection | FFN2a (x1 half) ----
__global__ void __launch_bounds__(256) mega_out2_ffn2a(
    const __nv_bfloat16* __restrict__ ctxb, const __nv_bfloat16* __restrict__ hidb1,
    const __nv_bfloat16* __restrict__ wb,
    const float* __restrict__ bout2, const float* __restrict__ fb2,
    float* __restrict__ proj, float* __restrict__ ffn1)
{
  extern __shared__ char gsm[];
  const int bx = blockIdx.x, by = blockIdx.y;
  if (bx < 4) {        // out2: ctxb @ Wo2 -> proj [8192,512]
    gemm_dev(ctxb, wb + WB_WO2, bout2, proj, nullptr, 16, D, D, D, 0,
             bx, by, gsm);
  } else {             // FFN2a: hidb1 @ fw2 -> ffn1 [8192,512]
    gemm_dev(hidb1, wb + WB_F2, fb2, ffn1, nullptr, 32, 2*D, 2*D, D, 0,
             bx - 4, by, gsm);
  }
}

// ======================= fused attention v2 (unchanged) ====================
#define FA_QS   0
#define FA_KS   18432
#define FA_VS   55296
#define FA_ZS   73728
#define FA_SMEM 74240
#define FA_KSTRIDE 18432

__global__ void __launch_bounds__(256, 2) fused_attn(
    const __nv_bfloat16* __restrict__ Q, const __nv_bfloat16* __restrict__ KV,
    float* __restrict__ attn, __nv_bfloat16* __restrict__ ctxb)
{
  extern __shared__ char sm[];
  float* Zs = (float*)(sm + FA_ZS);

  const int tid = threadIdx.x;
  const int wid = tid >> 5, l = tid & 31;
  const int gid = l >> 2, tig = l & 3;

  const int z = blockIdx.y;
  const int b = z >> 3, h = z & 7;
  const int l0 = blockIdx.x * 128;

  const __nv_bfloat16* Qg = Q  + (size_t)b * LSEQ * D + h * HD;
  const __nv_bfloat16* Kg = KV + (size_t)b * LSEQ * 2 * D + h * HD;
  const __nv_bfloat16* Vg = Kg + D;
  float* Pg = attn + (size_t)z * LSEQ * LSEQ;
  __nv_bfloat16* Ogb = ctxb + (size_t)b * LSEQ * D + h * HD;

  const uint32_t qsb = smem_u32(sm + FA_QS);
  const uint32_t ks0 = smem_u32(sm + FA_KS);
  const uint32_t vsb = smem_u32(sm + FA_VS);

  auto issue_q = [&]() {
    #pragma unroll
    for (int it = 0; it < 4; ++it) {
      int idx = tid + it * 256;
      int r = idx >> 3, c = (idx & 7) << 3;
      CP_ASYNC16(qsb + (uint32_t)(r * 144 + c * 2),
                 Qg + (size_t)(l0 + r) * D + c);
    }
    CP_COMMIT();
  };
  auto issue_k = [&](int s0, int kb) {
    const uint32_t base = ks0 + kb * FA_KSTRIDE;
    #pragma unroll
    for (int it = 0; it < 4; ++it) {
      int idx = tid + it * 256;
      int r = idx >> 3, c = (idx & 7) << 3;
      CP_ASYNC16(base + (uint32_t)(r * 144 + c * 2),
                 Kg + (size_t)(s0 + r) * 2 * D + c);
    }
    CP_COMMIT();
  };
  auto issue_v = [&](int s0) {
    #pragma unroll
    for (int it = 0; it < 4; ++it) {
      int idx = tid + it * 256;
      int r = idx >> 3, c = (idx & 7) << 3;
      CP_ASYNC16(vsb + (uint32_t)(r * 144 + c * 2),
                 Vg + (size_t)(s0 + r) * 2 * D + c);
    }
    CP_COMMIT();
  };

  issue_q();
  issue_k(0, 0);

  auto s_half = [&](float (*acc)[4], int kb, int half) {
    const uint32_t ksb = ks0 + kb * FA_KSTRIDE;
    #pragma unroll
    for (int j = 0; j < 8; j++)
      #pragma unroll
      for (int k = 0; k < 4; k++) acc[j][k] = 0.f;
    #pragma unroll
    for (int ks = 0; ks < 4; ks++) {
      const int k0 = ks * 16;
      uint32_t afr[4];
      {
        int row = wid * 16 + (l & 15);
        uint32_t addr = qsb + (uint32_t)(row * 144 + (k0 + ((l >> 4) << 3)) * 2);
        LDSM_X4(afr[0], afr[1], afr[2], afr[3], addr);
      }
      uint32_t bfr[8][2];
      #pragma unroll
      for (int nf = 0; nf < 8; nf += 2) {
        int row = half * 64 + nf * 8 + ((l >> 4) << 3) + (l & 7);
        int col = k0 + ((l >> 3) & 1) * 8;
        uint32_t addr = ksb + (uint32_t)(row * 144 + col * 2);
        LDSM_X4(bfr[nf][0], bfr[nf][1], bfr[nf + 1][0], bfr[nf + 1][1], addr);
      }
      #pragma unroll
      for (int nf = 0; nf < 8; nf++)
        MMA_BF16(acc[nf], afr, bfr[nf]);
    }
  };

  // pass 1: row sums
  {
    float zr[2] = {0.f, 0.f};
    for (int st = 0; st < 8; st++) {
      const int kb = st & 1;
      CP_WAIT(0);
      __syncthreads();
      if (st < 7) issue_k((st + 1) * 128, kb ^ 1); else CP_COMMIT();
      #pragma unroll
      for (int half = 0; half < 2; half++) {
        float acc[8][4];
        s_half(acc, kb, half);
        #pragma unroll
        for (int nf = 0; nf < 8; nf++) {
          zr[0] += __expf(acc[nf][0] * 0.125f) + __expf(acc[nf][1] * 0.125f);
          zr[1] += __expf(acc[nf][2] * 0.125f) + __expf(acc[nf][3] * 0.125f);
        }
      }
    }
    #pragma unroll
    for (int rp = 0; rp < 2; rp++) {
      float v = zr[rp];
      v += __shfl_xor_sync(0xffffffffu, v, 1);
      v += __shfl_xor_sync(0xffffffffu, v, 2);
      if (tig == 0) Zs[wid * 16 + rp * 8 + gid] = v;
    }
    __syncthreads();
    if (tid < 128) Zs[tid] = 1.f / Zs[tid];
    issue_k(0, 0);
    issue_v(0);
    __syncthreads();
  }

  float iz[2];
  iz[0] = Zs[wid * 16 + gid];
  iz[1] = Zs[wid * 16 + 8 + gid];

  // pass 2: write P, accumulate O = P@V
  float oacc[8][4];
  #pragma unroll
  for (int j = 0; j < 8; j++)
    #pragma unroll
    for (int k = 0; k < 4; k++) oacc[j][k] = 0.f;

  for (int st = 0; st < 8; st++) {
    const int s0 = st * 128;
    const int kb = st & 1;
    CP_WAIT(1);
    __syncthreads();
    if (st < 7) issue_k(s0 + 128, kb ^ 1); else CP_COMMIT();

    uint32_t pk[8][4];
    #pragma unroll
    for (int half = 0; half < 2; half++) {
      float acc[8][4];
      s_half(acc, kb, half);
      #pragma unroll
      for (int nf = 0; nf < 8; nf++) {
        const int gnf = half * 8 + nf;
        const int c = gnf * 8 + tig * 2;
        const int r0 = wid * 16 + gid;
        float p00 = __expf(acc[nf][0] * 0.125f) * iz[0];
        float p01 = __expf(acc[nf][1] * 0.125f) * iz[0];
        float p10 = __expf(acc[nf][2] * 0.125f) * iz[1];
        float p11 = __expf(acc[nf][3] * 0.125f) * iz[1];
        *(float2*)(Pg + (size_t)(l0 + r0) * LSEQ + s0 + c) = make_float2(p00, p01);
        *(float2*)(Pg + (size_t)(l0 + r0 + 8) * LSEQ + s0 + c) = make_float2(p10, p11);
        __nv_bfloat162 q0 = __floats2bfloat162_rn(p00, p01);
        __nv_bfloat162 q1 = __floats2bfloat162_rn(p10, p11);
        const int kk = gnf >> 1;
        if ((gnf & 1) == 0) {
          pk[kk][0] = *(uint32_t*)&q0;
          pk[kk][1] = *(uint32_t*)&q1;
        } else {
          pk[kk][2] = *(uint32_t*)&q0;
          pk[kk][3] = *(uint32_t*)&q1;
        }
      }
    }
    CP_WAIT(1);
    __syncthreads();

    #pragma unroll
    for (int kk = 0; kk < 8; kk++) {
      uint32_t bfr[8][2];
      #pragma unroll
      for (int nf = 0; nf < 8; nf += 2) {
        int krow = kk * 16 + ((l >> 3) & 1) * 8 + (l & 7);
        int ncol = nf * 8 + ((l >> 4) << 3);
        uint32_t addr = vsb + (uint32_t)(krow * 144 + ncol * 2);
        LDSM_X4_T(bfr[nf][0], bfr[nf][1], bfr[nf + 1][0], bfr[nf + 1][1], addr);
      }
      #pragma unroll
      for (int nf = 0; nf < 8; nf++)
        MMA_BF16(oacc[nf], pk[kk], bfr[nf]);
    }
    __syncthreads();
    if (st < 7) issue_v(s0 + 128); else CP_COMMIT();
  }
  CP_WAIT(0);

  {
    const int r0 = l0 + wid * 16 + gid;
    #pragma unroll
    for (int nf = 0; nf < 8; nf++) {
      const int c = nf * 8 + tig * 2;
      __nv_bfloat162 h0 = __floats2bfloat162_rn(oacc[nf][0], oacc[nf][1]);
      __nv_bfloat162 h1 = __floats2bfloat162_rn(oacc[nf][2], oacc[nf][3]);
      *(uint32_t*)(Ogb + (size_t)r0 * D + c) = *(uint32_t*)&h0;
      *(uint32_t*)(Ogb + (size_t)(r0 + 8) * D + c) = *(uint32_t*)&h1;
    }
  }
}

// ---------------- residual + LN device core ----------------
__device__ __forceinline__ void ln_dev(
    const float* __restrict__ x, const float* __restrict__ y,
    const float* __restrict__ g, const float* __restrict__ b,
    float* __restrict__ out, __nv_bfloat16* __restrict__ outb, size_t row)
{
  __shared__ float shs[8], shq[8];
  const int t = threadIdx.x;
  float2 xa = ((const float2*)x)[row * 256 + t];
  float2 ya = ((const float2*)y)[row * 256 + t];
  float v0 = xa.x + ya.x, v1 = xa.y + ya.y;
  float s = v0 + v1, q = v0*v0 + v1*v1;
  #pragma unroll
  for (int o = 16; o > 0; o >>= 1) {
    s += __shfl_xor_sync(0xffffffffu, s, o);
    q += __shfl_xor_sync(0xffffffffu, q, o);
  }
  if ((t & 31) == 0) { shs[t >> 5] = s; shq[t >> 5] = q; }
  __syncthreads();
  s = 0.f; q = 0.f;
  #pragma unroll
  for (int i = 0; i < 8; i++) { s += shs[i]; q += shq[i]; }
  float mu  = s * (1.f / 512.f);
  float var = q * (1.f / 512.f) - mu * mu;
  float inv = rsqrtf(var + 1e-5f);
  float2 gg = ((const float2*)g)[t];
  float2 bb = ((const float2*)b)[t];
  float2 o2;
  o2.x = (v0 - mu) * inv * gg.x + bb.x;
  o2.y = (v1 - mu) * inv * gg.y + bb.y;
  ((float2*)out)[row * 256 + t] = o2;
  if (outb) {
    __nv_bfloat162 h = __floats2bfloat162_rn(o2.x, o2.y);
    ((uint32_t*)outb)[row * 256 + t] = *(uint32_t*)&h;
  }
}

__global__ void __launch_bounds__(256) residual_ln_kernel(
    const float* __restrict__ x, const float* __restrict__ y,
    const float* __restrict__ g, const float* __restrict__ b,
    float* __restrict__ out, __nv_bfloat16* __restrict__ outb)
{
  ln_dev(x, y, g, b, out, outb, blockIdx.x);
}

// merged: LN2 (x2 + proj) | LN3a (ox1 + ffn_a, in place)
__global__ void __launch_bounds__(256) ln2_ln3a(
    const float* __restrict__ x2, const float* __restrict__ proj,
    const float* __restrict__ g2, const float* __restrict__ b2,
    float* __restrict__ ox2, __nv_bfloat16* __restrict__ xlnb2,
    float* __restrict__ ox1, const float* __restrict__ ffn1,
    const float* __restrict__ g3, const float* __restrict__ b3)
{
  size_t r = blockIdx.x;
  if (r < ROWS) ln_dev(x2, proj, g2, b2, ox2, xlnb2, r);
  else          ln_dev(ox1, ffn1, g3, b3, ox1, nullptr, r - ROWS);
}

// ---------------- host-side orchestration ----------------
extern "C" void kernel_launch(void* const* d_in, const int* in_sizes, int n_in,
                              void* d_out, int out_size)
{
  const float* x1    = (const float*)d_in[0];
  const float* x2    = (const float*)d_in[1];
  const float* win1  = (const float*)d_in[2];
  const float* bin1  = (const float*)d_in[3];
  const float* wout1 = (const float*)d_in[4];
  const float* bout1 = (const float*)d_in[5];
  const float* win2  = (const float*)d_in[6];
  const float* bin2  = (const float*)d_in[7];
  const float* wout2 = (const float*)d_in[8];
  const float* bout2 = (const float*)d_in[9];
  const float* g1    = (const float*)d_in[10];
  const float* b1    = (const float*)d_in[11];
  const float* g2    = (const float*)d_in[12];
  const float* b2    = (const float*)d_in[13];
  const float* fw1   = (const float*)d_in[14];
  const float* fb1   = (const float*)d_in[15];
  const float* fw2   = (const float*)d_in[16];
  const float* fb2   = (const float*)d_in[17];
  const float* g3    = (const float*)d_in[18];
  const float* b3    = (const float*)d_in[19];

  cudaFuncSetAttribute(fused_attn, cudaFuncAttributeMaxDynamicSharedMemorySize, FA_SMEM);
  cudaFuncSetAttribute(gemm_k,          cudaFuncAttributeMaxDynamicSharedMemorySize, GE_SMEM);
  cudaFuncSetAttribute(mega_qkv,        cudaFuncAttributeMaxDynamicSharedMemorySize, GE_SMEM);
  cudaFuncSetAttribute(mega_kv2_ffn1a,  cudaFuncAttributeMaxDynamicSharedMemorySize, GE_SMEM);
  cudaFuncSetAttribute(mega_out2_ffn2a, cudaFuncAttributeMaxDynamicSharedMemorySize, GE_SMEM);

  float* out = (float*)d_out;
  float* ox1 = out;
  float* ox2 = out + (size_t)ROWS * D;
  float* w12 = out + (size_t)2 * ROWS * D;
  float* w21 = w12 + (size_t)BH * LSEQ * LSEQ;

  __nv_bfloat16 *x1b, *x2b, *qb, *kvb, *ctxb, *hidb, *xlnb, *wb;
  float *proj, *ffn;
  cudaGetSymbolAddress((void**)&x1b,  g_x1b);
  cudaGetSymbolAddress((void**)&x2b,  g_x2b);
  cudaGetSymbolAddress((void**)&qb,   g_qb);
  cudaGetSymbolAddress((void**)&kvb,  g_kvb);
  cudaGetSymbolAddress((void**)&ctxb, g_ctxb);
  cudaGetSymbolAddress((void**)&hidb, g_hidb);
  cudaGetSymbolAddress((void**)&xlnb, g_xlnb);
  cudaGetSymbolAddress((void**)&wb,   g_wb);
  cudaGetSymbolAddress((void**)&proj, g_proj);
  cudaGetSymbolAddress((void**)&ffn,  g_ffn);

  __nv_bfloat16* qb2   = qb + (size_t)ROWS * D;
  __nv_bfloat16* xlnb2 = xlnb + (size_t)ROWS * D;
  __nv_bfloat16* hidb1 = hidb;                               // x1 half
  __nv_bfloat16* hidb2 = hidb + (size_t)ROWS * 2 * D;        // x2 half
  float* ffn1 = ffn;                                         // x1 half
  float* ffn2 = ffn + (size_t)ROWS * D;                      // x2 half

  convert_all<<<CV_BLOCKS, 256>>>(x1, x2, win1, wout1, win2, wout2,          // 0
                                  fw1, fw2, x1b, x2b, wb);
  mega_qkv<<<dim3(16, 32), 256, GE_SMEM>>>(x1b, x2b, wb, bin1, bin2,         // 1
                                           qb, qb2, kvb);
  fused_attn<<<dim3(8, BH), 256, FA_SMEM>>>(qb, kvb, w12, ctxb);             // 2
  gemm_k<<<dim3(4, 32), 256, GE_SMEM>>>(ctxb, wb + WB_WO1, bout1, proj,      // 3
                                        nullptr, 16, D, D, D, 0);
  residual_ln_kernel<<<ROWS, 256>>>(x1, proj, g1, b1, ox1, xlnb);            // 4
  mega_kv2_ffn1a<<<dim3(16, 32), 256, GE_SMEM>>>(xlnb, wb, bin2, fb1,        // 5
                                                 kvb, hidb1);
  fused_attn<<<dim3(8, BH), 256, FA_SMEM>>>(qb2, kvb, w21, ctxb);            // 6
  mega_out2_ffn2a<<<dim3(8, 32), 256, GE_SMEM>>>(ctxb, hidb1, wb,            // 7
                                                 bout2, fb2, proj, ffn1);
  ln2_ln3a<<<2 * ROWS, 256>>>(x2, proj, g2, b2, ox2, xlnb2,                  // 8
                              ox1, ffn1, g3, b3);
  gemm_k<<<dim3(8, 32), 256, GE_SMEM>>>(xlnb2, wb + WB_F1, fb1,              // 9
                                        nullptr, hidb2, 16, D, D, 2*D, 1);
  gemm_k<<<dim3(4, 32), 256, GE_SMEM>>>(hidb2, wb + WB_F2, fb2, ffn2,        // 10
                                        nullptr, 32, 2*D, 2*D, D, 0);
  residual_ln_kernel<<<ROWS, 256>>>(ox2, ffn2, g3, b3, ox2, nullptr);        // 11
}

// round 11
// speedup vs baseline: 1.0783x; 1.0783x over previous
#include <cuda_runtime.h>
#include <cuda_bf16.h>
#include <math.h>
#include <stddef.h>
#include <stdint.h>

#define D 512
#define LSEQ 1024
#define BATCH 8
#define NH 8
#define HD 64
#define ROWS (BATCH*LSEQ)   /* 8192 */
#define BH (BATCH*NH)       /* 64   */
#define DD (D*D)

// ---------------- scratch (no allocations allowed) ----------------
__device__ __nv_bfloat16 g_x1b[ROWS*D];
__device__ __nv_bfloat16 g_x2b[ROWS*D];
__device__ __nv_bfloat16 g_qb[(size_t)2*ROWS*D];
__device__ __nv_bfloat16 g_kvb[(size_t)ROWS*2*D];
__device__ __nv_bfloat16 g_ctxb[ROWS*D];
__device__ __nv_bfloat16 g_hidb[(size_t)2*ROWS*2*D];
__device__ __nv_bfloat16 g_xlnb[(size_t)2*ROWS*D];
__device__ __nv_bfloat16 g_wb[(size_t)12*DD];
__device__ float g_proj[ROWS*D];
__device__ float g_ffn[(size_t)2*ROWS*D];

#define WB_W1  0
#define WB_WO1 (3*DD)
#define WB_W2  (4*DD)
#define WB_WO2 (7*DD)
#define WB_F1  (8*DD)
#define WB_F2  (10*DD)

// ======================= helpers =======================
__device__ __forceinline__ uint32_t smem_u32(const void* p) {
  uint32_t a;
  asm("{ .reg .u64 t; cvta.to.shared.u64 t, %1; cvt.u32.u64 %0, t; }"
      : "=r"(a) : "l"(p));
  return a;
}

#define CP_ASYNC16(dst, src) \
  asm volatile("cp.async.cg.shared.global [%0], [%1], 16;" \
               :: "r"(dst), "l"(src))
#define CP_COMMIT() asm volatile("cp.async.commit_group;")
#define CP_WAIT(n)  asm volatile("cp.async.wait_group %0;" :: "n"(n))

#define LDSM_X4(r0, r1, r2, r3, addr) \
  asm volatile("ldmatrix.sync.aligned.m8n8.x4.shared.b16 {%0,%1,%2,%3}, [%4];" \
               : "=r"(r0), "=r"(r1), "=r"(r2), "=r"(r3) : "r"(addr))
#define LDSM_X4_T(r0, r1, r2, r3, addr) \
  asm volatile("ldmatrix.sync.aligned.m8n8.x4.trans.shared.b16 {%0,%1,%2,%3}, [%4];" \
               : "=r"(r0), "=r"(r1), "=r"(r2), "=r"(r3) : "r"(addr))

#define MMA_BF16(c, a, b) \
  asm volatile( \
    "mma.sync.aligned.m16n8k16.row.col.f32.bf16.bf16.f32 " \
    "{%0,%1,%2,%3}, {%4,%5,%6,%7}, {%8,%9}, {%0,%1,%2,%3};" \
    : "+f"((c)[0]), "+f"((c)[1]), "+f"((c)[2]), "+f"((c)[3]) \
    : "r"((a)[0]), "r"((a)[1]), "r"((a)[2]), "r"((a)[3]), \
      "r"((b)[0]), "r"((b)[1]))

// streaming fp32x2 store (write-once data, evict-first)
__device__ __forceinline__ void stcs_f2(float* p, float2 v) {
  asm volatile("st.global.cs.v2.f32 [%0], {%1, %2};" :: "l"(p), "f"(v.x), "f"(v.y));
}

// ---------------- all fp32 -> bf16 converts in ONE launch -----------------
#define CV_Q4   (ROWS*D/4)
#define CV_C3   (3*DD/4)
#define CV_C1   (DD/4)
#define CV_C2   (2*DD/4)
#define CV_WTOT (12*DD/4)
#define CV_TOT  (2*CV_Q4 + CV_WTOT)
#define CV_BLOCKS (CV_TOT/256)

__global__ void __launch_bounds__(256) convert_all(
    const float* __restrict__ x1, const float* __restrict__ x2,
    const float* __restrict__ win1, const float* __restrict__ wout1,
    const float* __restrict__ win2, const float* __restrict__ wout2,
    const float* __restrict__ fw1, const float* __restrict__ fw2,
    __nv_bfloat16* __restrict__ x1b, __nv_bfloat16* __restrict__ x2b,
    __nv_bfloat16* __restrict__ wb)
{
  long i = (long)blockIdx.x * 256 + threadIdx.x;
  const float* src;
  __nv_bfloat16* dstb;
  long off, sidx;
  if (i < CV_Q4) { src = x1; dstb = x1b; off = i; sidx = i; }
  else if (i < 2 * CV_Q4) { src = x2; dstb = x2b; off = i - CV_Q4; sidx = off; }
  else {
    long w = i - 2 * CV_Q4;
    dstb = wb; sidx = w;
    if      (w < CV_C3)                 { src = win1;  off = w; }
    else if (w < CV_C3 + CV_C1)         { src = wout1; off = w - CV_C3; }
    else if (w < 2*CV_C3 + CV_C1)       { src = win2;  off = w - (CV_C3 + CV_C1); }
    else if (w < 2*CV_C3 + 2*CV_C1)     { src = wout2; off = w - (2*CV_C3 + CV_C1); }
    else if (w < 2*CV_C3 + 2*CV_C1 + CV_C2) { src = fw1; off = w - (2*CV_C3 + 2*CV_C1); }
    else                                { src = fw2;  off = w - (2*CV_C3 + 2*CV_C1 + CV_C2); }
  }
  float4 v = ((const float4*)src)[off];
  __nv_bfloat162 a = __floats2bfloat162_rn(v.x, v.y);
  __nv_bfloat162 b = __floats2bfloat162_rn(v.z, v.w);
  ((uint2*)dstb)[sidx] = make_uint2(*(uint32_t*)&a, *(uint32_t*)&b);
}

// ======================= bf16 GEMM (R6 config: 128x128, 4-stage, slab 32) ==
__global__ void __launch_bounds__(256) gemm_bf16(
    const __nv_bfloat16* __restrict__ A, const __nv_bfloat16* __restrict__ B,
    const float* __restrict__ bias, float* __restrict__ Cf,
    __nv_bfloat16* __restrict__ Cb,
    int nslab, int lda, int ldb, int ldc, int relu)
{
  __shared__ __align__(16) __nv_bfloat16 As[4][128][40];
  __shared__ __align__(16) __nv_bfloat16 Bs[4][128][40];

  const int tid = threadIdx.x;
  const int wid = tid >> 5, l = tid & 31;
  const int warp_m = wid & 3, warp_n = wid >> 2;

  const int bm = blockIdx.y * 128;
  const int bn = blockIdx.x * 128;

  float acc[2][8][4];
  #pragma unroll
  for (int i = 0; i < 2; i++)
    #pragma unroll
    for (int j = 0; j < 8; j++)
      #pragma unroll
      for (int k = 0; k < 4; k++) acc[i][j][k] = 0.f;

  auto issue = [&](int slab, int stg) {
    const int k0 = slab << 5;
    #pragma unroll
    for (int it = 0; it < 2; ++it) {
      int idx = tid + it * 256;
      int r = idx >> 2, c = (idx & 3) << 3;
      CP_ASYNC16(smem_u32(&As[stg][r][c]),
                 A + (size_t)(bm + r) * lda + k0 + c);
    }
    #pragma unroll
    for (int it = 0; it < 2; ++it) {
      int idx = tid + it * 256;
      int r = idx >> 2, c = (idx & 3) << 3;
      CP_ASYNC16(smem_u32(&Bs[stg][r][c]),
                 B + (size_t)(bn + r) * ldb + k0 + c);
    }
    CP_COMMIT();
  };

  #pragma unroll
  for (int s = 0; s < 3; s++) {
    if (s < nslab) issue(s, s); else CP_COMMIT();
  }

  for (int i = 0; i < nslab; i++) {
    CP_WAIT(2);
    __syncthreads();
    const int buf = i & 3;
    if (i + 3 < nslab) issue(i + 3, (i + 3) & 3); else CP_COMMIT();

    const uint32_t a_base = smem_u32(&As[buf][0][0]);
    const uint32_t b_base = smem_u32(&Bs[buf][0][0]);
    #pragma unroll
    for (int ks = 0; ks < 2; ks++) {
      const int k0 = ks * 16;
      uint32_t afr[2][4];
      #pragma unroll
      for (int mf = 0; mf < 2; mf++) {
        int row = warp_m * 32 + mf * 16 + (l & 15);
        uint32_t addr = a_base + (uint32_t)(row * 80 + (k0 + ((l >> 4) << 3)) * 2);
        LDSM_X4(afr[mf][0], afr[mf][1], afr[mf][2], afr[mf][3], addr);
      }
      uint32_t bfr[8][2];
      #pragma unroll
      for (int nf = 0; nf < 8; nf += 2) {
        int row = warp_n * 64 + nf * 8 + ((l >> 4) << 3) + (l & 7);
        int col = k0 + ((l >> 3) & 1) * 8;
        uint32_t addr = b_base + (uint32_t)(row * 80 + col * 2);
        LDSM_X4(bfr[nf][0], bfr[nf][1], bfr[nf + 1][0], bfr[nf + 1][1], addr);
      }
      #pragma unroll
      for (int mf = 0; mf < 2; mf++)
        #pragma unroll
        for (int nf = 0; nf < 8; nf++)
          MMA_BF16(acc[mf][nf], afr[mf], bfr[nf]);
    }
  }

  const int gid = l >> 2, tig = l & 3;
  #pragma unroll
  for (int mf = 0; mf < 2; mf++) {
    const int row = bm + warp_m * 32 + mf * 16 + gid;
    #pragma unroll
    for (int nf = 0; nf < 8; nf++) {
      const int col = bn + warp_n * 64 + nf * 8 + tig * 2;
      float2 bv = make_float2(0.f, 0.f);
      if (bias) bv = *(const float2*)(bias + col);
      float2 v0, v1;
      v0.x = acc[mf][nf][0] + bv.x;
      v0.y = acc[mf][nf][1] + bv.y;
      v1.x = acc[mf][nf][2] + bv.x;
      v1.y = acc[mf][nf][3] + bv.y;
      if (relu) {
        v0.x = fmaxf(v0.x, 0.f); v0.y = fmaxf(v0.y, 0.f);
        v1.x = fmaxf(v1.x, 0.f); v1.y = fmaxf(v1.y, 0.f);
      }
      if (Cf) {
        *(float2*)(Cf + (size_t)row * ldc + col) = v0;
        *(float2*)(Cf + (size_t)(row + 8) * ldc + col) = v1;
      }
      if (Cb) {
        __nv_bfloat162 h0 = __floats2bfloat162_rn(v0.x, v0.y);
        __nv_bfloat162 h1 = __floats2bfloat162_rn(v1.x, v1.y);
        *(uint32_t*)(Cb + (size_t)row * ldc + col) = *(uint32_t*)&h0;
        *(uint32_t*)(Cb + (size_t)(row + 8) * ldc + col) = *(uint32_t*)&h1;
      }
    }
  }
}

// ======================= fused attention (R6 config) =======================
#define FA_QS   0
#define FA_KS   18432
#define FA_VS   55296
#define FA_ZS   73728
#define FA_SMEM 74240
#define FA_KSTRIDE 18432

__global__ void __launch_bounds__(256, 2) fused_attn(
    const __nv_bfloat16* __restrict__ Q, const __nv_bfloat16* __restrict__ KV,
    float* __restrict__ attn, __nv_bfloat16* __restrict__ ctxb)
{
  extern __shared__ char sm[];
  float* Zs = (float*)(sm + FA_ZS);

  const int tid = threadIdx.x;
  const int wid = tid >> 5, l = tid & 31;
  const int gid = l >> 2, tig = l & 3;

  const int z = blockIdx.y;
  const int b = z >> 3, h = z & 7;
  const int l0 = blockIdx.x * 128;

  const __nv_bfloat16* Qg = Q  + (size_t)b * LSEQ * D + h * HD;
  const __nv_bfloat16* Kg = KV + (size_t)b * LSEQ * 2 * D + h * HD;
  const __nv_bfloat16* Vg = Kg + D;
  float* Pg = attn + (size_t)z * LSEQ * LSEQ;
  __nv_bfloat16* Ogb = ctxb + (size_t)b * LSEQ * D + h * HD;

  const uint32_t qsb = smem_u32(sm + FA_QS);
  const uint32_t ks0 = smem_u32(sm + FA_KS);
  const uint32_t vsb = smem_u32(sm + FA_VS);

  auto issue_q = [&]() {
    #pragma unroll
    for (int it = 0; it < 4; ++it) {
      int idx = tid + it * 256;
      int r = idx >> 3, c = (idx & 7) << 3;
      CP_ASYNC16(qsb + (uint32_t)(r * 144 + c * 2),
                 Qg + (size_t)(l0 + r) * D + c);
    }
    CP_COMMIT();
  };
  auto issue_k = [&](int s0, int kb) {
    const uint32_t base = ks0 + kb * FA_KSTRIDE;
    #pragma unroll
    for (int it = 0; it < 4; ++it) {
      int idx = tid + it * 256;
      int r = idx >> 3, c = (idx & 7) << 3;
      CP_ASYNC16(base + (uint32_t)(r * 144 + c * 2),
                 Kg + (size_t)(s0 + r) * 2 * D + c);
    }
    CP_COMMIT();
  };
  auto issue_v = [&](int s0) {
    #pragma unroll
    for (int it = 0; it < 4; ++it) {
      int idx = tid + it * 256;
      int r = idx >> 3, c = (idx & 7) << 3;
      CP_ASYNC16(vsb + (uint32_t)(r * 144 + c * 2),
                 Vg + (size_t)(s0 + r) * 2 * D + c);
    }
    CP_COMMIT();
  };

  issue_q();
  issue_k(0, 0);

  auto s_half = [&](float (*acc)[4], int kb, int half) {
    const uint32_t ksb = ks0 + kb * FA_KSTRIDE;
    #pragma unroll
    for (int j = 0; j < 8; j++)
      #pragma unroll
      for (int k = 0; k < 4; k++) acc[j][k] = 0.f;
    #pragma unroll
    for (int ks = 0; ks < 4; ks++) {
      const int k0 = ks * 16;
      uint32_t afr[4];
      {
        int row = wid * 16 + (l & 15);
        uint32_t addr = qsb + (uint32_t)(row * 144 + (k0 + ((l >> 4) << 3)) * 2);
        LDSM_X4(afr[0], afr[1], afr[2], afr[3], addr);
      }
      uint32_t bfr[8][2];
      #pragma unroll
      for (int nf = 0; nf < 8; nf += 2) {
        int row = half * 64 + nf * 8 + ((l >> 4) << 3) + (l & 7);
        int col = k0 + ((l >> 3) & 1) * 8;
        uint32_t addr = ksb + (uint32_t)(row * 144 + col * 2);
        LDSM_X4(bfr[nf][0], bfr[nf][1], bfr[nf + 1][0], bfr[nf + 1][1], addr);
      }
      #pragma unroll
      for (int nf = 0; nf < 8; nf++)
        MMA_BF16(acc[nf], afr, bfr[nf]);
    }
  };

  // pass 1: row sums
  {
    float zr[2] = {0.f, 0.f};
    for (int st = 0; st < 8; st++) {
      const int kb = st & 1;
      CP_WAIT(0);
      __syncthreads();
      if (st < 7) issue_k((st + 1) * 128, kb ^ 1); else CP_COMMIT();
      #pragma unroll
      for (int half = 0; half < 2; half++) {
        float acc[8][4];
        s_half(acc, kb, half);
        #pragma unroll
        for (int nf = 0; nf < 8; nf++) {
          zr[0] += __expf(acc[nf][0] * 0.125f) + __expf(acc[nf][1] * 0.125f);
          zr[1] += __expf(acc[nf][2] * 0.125f) + __expf(acc[nf][3] * 0.125f);
        }
      }
    }
    #pragma unroll
    for (int rp = 0; rp < 2; rp++) {
      float v = zr[rp];
      v += __shfl_xor_sync(0xffffffffu, v, 1);
      v += __shfl_xor_sync(0xffffffffu, v, 2);
      if (tig == 0) Zs[wid * 16 + rp * 8 + gid] = v;
    }
    __syncthreads();
    if (tid < 128) Zs[tid] = 1.f / Zs[tid];
    issue_k(0, 0);
    issue_v(0);
    __syncthreads();
  }

  float iz[2];
  iz[0] = Zs[wid * 16 + gid];
  iz[1] = Zs[wid * 16 + 8 + gid];

  // pass 2: write P (streaming), accumulate O = P@V
  float oacc[8][4];
  #pragma unroll
  for (int j = 0; j < 8; j++)
    #pragma unroll
    for (int k = 0; k < 4; k++) oacc[j][k] = 0.f;

  for (int st = 0; st < 8; st++) {
    const int s0 = st * 128;
    const int kb = st & 1;
    CP_WAIT(1);
    __syncthreads();
    if (st < 7) issue_k(s0 + 128, kb ^ 1); else CP_COMMIT();

    uint32_t pk[8][4];
    #pragma unroll
    for (int half = 0; half < 2; half++) {
      float acc[8][4];
      s_half(acc, kb, half);
      #pragma unroll
      for (int nf = 0; nf < 8; nf++) {
        const int gnf = half * 8 + nf;
        const int c = gnf * 8 + tig * 2;
        const int r0 = wid * 16 + gid;
        float p00 = __expf(acc[nf][0] * 0.125f) * iz[0];
        float p01 = __expf(acc[nf][1] * 0.125f) * iz[0];
        float p10 = __expf(acc[nf][2] * 0.125f) * iz[1];
        float p11 = __expf(acc[nf][3] * 0.125f) * iz[1];
        stcs_f2(Pg + (size_t)(l0 + r0) * LSEQ + s0 + c, make_float2(p00, p01));
        stcs_f2(Pg + (size_t)(l0 + r0 + 8) * LSEQ + s0 + c, make_float2(p10, p11));
        __nv_bfloat162 q0 = __floats2bfloat162_rn(p00, p01);
        __nv_bfloat162 q1 = __floats2bfloat162_rn(p10, p11);
        const int kk = gnf >> 1;
        if ((gnf & 1) == 0) {
          pk[kk][0] = *(uint32_t*)&q0;
          pk[kk][1] = *(uint32_t*)&q1;
        } else {
          pk[kk][2] = *(uint32_t*)&q0;
          pk[kk][3] = *(uint32_t*)&q1;
        }
      }
    }
    CP_WAIT(1);
    __syncthreads();

    #pragma unroll
    for (int kk = 0; kk < 8; kk++) {
      uint32_t bfr[8][2];
      #pragma unroll
      for (int nf = 0; nf < 8; nf += 2) {
        int krow = kk * 16 + ((l >> 3) & 1) * 8 + (l & 7);
        int ncol = nf * 8 + ((l >> 4) << 3);
        uint32_t addr = vsb + (uint32_t)(krow * 144 + ncol * 2);
        LDSM_X4_T(bfr[nf][0], bfr[nf][1], bfr[nf + 1][0], bfr[nf + 1][1], addr);
      }
      #pragma unroll
      for (int nf = 0; nf < 8; nf++)
        MMA_BF16(oacc[nf], pk[kk], bfr[nf]);
    }
    __syncthreads();
    if (st < 7) issue_v(s0 + 128); else CP_COMMIT();
  }
  CP_WAIT(0);

  {
    const int r0 = l0 + wid * 16 + gid;
    #pragma unroll
    for (int nf = 0; nf < 8; nf++) {
      const int c = nf * 8 + tig * 2;
      __nv_bfloat162 h0 = __floats2bfloat162_rn(oacc[nf][0], oacc[nf][1]);
      __nv_bfloat162 h1 = __floats2bfloat162_rn(oacc[nf][2], oacc[nf][3]);
      *(uint32_t*)(Ogb + (size_t)r0 * D + c) = *(uint32_t*)&h0;
      *(uint32_t*)(Ogb + (size_t)(r0 + 8) * D + c) = *(uint32_t*)&h1;
    }
  }
}

// ---------------- out = LN(x + y) * g + b, rows of 512 ----------------
__global__ void __launch_bounds__(256) residual_ln_kernel(
    const float* __restrict__ x, const float* __restrict__ y,
    const float* __restrict__ g, const float* __restrict__ b,
    float* __restrict__ out, __nv_bfloat16* __restrict__ outb)
{
  __shared__ float shs[8], shq[8];
  const size_t row = blockIdx.x;
  const int t = threadIdx.x;
  float2 xa = ((const float2*)x)[row * 256 + t];
  float2 ya = ((const float2*)y)[row * 256 + t];
  float v0 = xa.x + ya.x, v1 = xa.y + ya.y;
  float s = v0 + v1, q = v0*v0 + v1*v1;
  #pragma unroll
  for (int o = 16; o > 0; o >>= 1) {
    s += __shfl_xor_sync(0xffffffffu, s, o);
    q += __shfl_xor_sync(0xffffffffu, q, o);
  }
  if ((t & 31) == 0) { shs[t >> 5] = s; shq[t >> 5] = q; }
  __syncthreads();
  s = 0.f; q = 0.f;
  #pragma unroll
  for (int i = 0; i < 8; i++) { s += shs[i]; q += shq[i]; }
  float mu  = s * (1.f / 512.f);
  float var = q * (1.f / 512.f) - mu * mu;
  float inv = rsqrtf(var + 1e-5f);
  float2 gg = ((const float2*)g)[t];
  float2 bb = ((const float2*)b)[t];
  float2 o2;
  o2.x = (v0 - mu) * inv * gg.x + bb.x;
  o2.y = (v1 - mu) * inv * gg.y + bb.y;
  ((float2*)out)[row * 256 + t] = o2;
  if (outb) {
    __nv_bfloat162 h = __floats2bfloat162_rn(o2.x, o2.y);
    ((uint32_t*)outb)[row * 256 + t] = *(uint32_t*)&h;
  }
}

// ---------------- host-side orchestration ----------------
extern "C" void kernel_launch(void* const* d_in, const int* in_sizes, int n_in,
                              void* d_out, int out_size)
{
  const float* x1    = (const float*)d_in[0];
  const float* x2    = (const float*)d_in[1];
  const float* win1  = (const float*)d_in[2];
  const float* bin1  = (const float*)d_in[3];
  const float* wout1 = (const float*)d_in[4];
  const float* bout1 = (const float*)d_in[5];
  const float* win2  = (const float*)d_in[6];
  const float* bin2  = (const float*)d_in[7];
  const float* wout2 = (const float*)d_in[8];
  const float* bout2 = (const float*)d_in[9];
  const float* g1    = (const float*)d_in[10];
  const float* b1    = (const float*)d_in[11];
  const float* g2    = (const float*)d_in[12];
  const float* b2    = (const float*)d_in[13];
  const float* fw1   = (const float*)d_in[14];
  const float* fb1   = (const float*)d_in[15];
  const float* fw2   = (const float*)d_in[16];
  const float* fb2   = (const float*)d_in[17];
  const float* g3    = (const float*)d_in[18];
  const float* b3    = (const float*)d_in[19];

  cudaFuncSetAttribute(fused_attn, cudaFuncAttributeMaxDynamicSharedMemorySize, FA_SMEM);

  float* out = (float*)d_out;
  float* ox1 = out;
  float* ox2 = out + (size_t)ROWS * D;
  float* w12 = out + (size_t)2 * ROWS * D;
  float* w21 = w12 + (size_t)BH * LSEQ * LSEQ;

  __nv_bfloat16 *x1b, *x2b, *qb, *kvb, *ctxb, *hidb, *xlnb, *wb;
  float *proj, *ffn;
  cudaGetSymbolAddress((void**)&x1b,  g_x1b);
  cudaGetSymbolAddress((void**)&x2b,  g_x2b);
  cudaGetSymbolAddress((void**)&qb,   g_qb);
  cudaGetSymbolAddress((void**)&kvb,  g_kvb);
  cudaGetSymbolAddress((void**)&ctxb, g_ctxb);
  cudaGetSymbolAddress((void**)&hidb, g_hidb);
  cudaGetSymbolAddress((void**)&xlnb, g_xlnb);
  cudaGetSymbolAddress((void**)&wb,   g_wb);
  cudaGetSymbolAddress((void**)&proj, g_proj);
  cudaGetSymbolAddress((void**)&ffn,  g_ffn);

  __nv_bfloat16* qb2 = qb + (size_t)ROWS * D;

  convert_all<<<CV_BLOCKS, 256>>>(x1, x2, win1, wout1, win2, wout2,          // 0
                                  fw1, fw2, x1b, x2b, wb);
  // mha1 (Q2 hoisted: independent, fills the tail of the qkv phase)
  gemm_bf16<<<dim3(4, 64), 256>>>(x1b, wb + WB_W1, bin1, nullptr, qb,        // 1
                                  16, D, D, D, 0);
  gemm_bf16<<<dim3(8, 64), 256>>>(x2b, wb + WB_W1 + DD, bin1 + D,            // 2
                                  nullptr, kvb, 16, D, D, 2*D, 0);
  gemm_bf16<<<dim3(4, 64), 256>>>(x2b, wb + WB_W2, bin2, nullptr, qb2,       // 3
                                  16, D, D, D, 0);
  fused_attn<<<dim3(8, BH), 256, FA_SMEM>>>(qb, kvb, w12, ctxb);             // 4
  gemm_bf16<<<dim3(4, 64), 256>>>(ctxb, wb + WB_WO1, bout1, proj, nullptr,   // 5
                                  16, D, D, D, 0);
  residual_ln_kernel<<<ROWS, 256>>>(x1, proj, g1, b1, ox1, xlnb);            // 6

  // mha2
  gemm_bf16<<<dim3(8, 64), 256>>>(xlnb, wb + WB_W2 + DD, bin2 + D,           // 7
                                  nullptr, kvb, 16, D, D, 2*D, 0);
  fused_attn<<<dim3(8, BH), 256, FA_SMEM>>>(qb2, kvb, w21, ctxb);            // 8
  gemm_bf16<<<dim3(4, 64), 256>>>(ctxb, wb + WB_WO2, bout2, proj, nullptr,   // 9
                                  16, D, D, D, 0);
  residual_ln_kernel<<<ROWS, 256>>>(x2, proj, g2, b2, ox2,                   // 10
                                    xlnb + (size_t)ROWS * D);

  // FFN over both streams
  gemm_bf16<<<dim3(8, 128), 256>>>(xlnb, wb + WB_F1, fb1, nullptr, hidb,     // 11
                                   16, D, D, 2*D, 1);
  gemm_bf16<<<dim3(4, 128), 256>>>(hidb, wb + WB_F2, fb2, ffn, nullptr,      // 12
                                   32, 2*D, 2*D, D, 0);
  residual_ln_kernel<<<2*ROWS, 256>>>(out, ffn, g3, b3, out, nullptr);       // 13
}

// round 12
// speedup vs baseline: 1.1371x; 1.0545x over previous
#include <cuda_runtime.h>
#include <cuda_bf16.h>
#include <math.h>
#include <stddef.h>
#include <stdint.h>

#define D 512
#define LSEQ 1024
#define BATCH 8
#define NH 8
#define HD 64
#define ROWS (BATCH*LSEQ)   /* 8192 */
#define BH (BATCH*NH)       /* 64   */
#define DD (D*D)

// ---------------- scratch (no allocations allowed) ----------------
__device__ __nv_bfloat16 g_x1b[ROWS*D];
__device__ __nv_bfloat16 g_x2b[ROWS*D];
__device__ __nv_bfloat16 g_qb[ROWS*D];                 // mha1 Q
__device__ __nv_bfloat16 g_kq[(size_t)ROWS*3*D];       // mha1 [K|V|Q2], ld 1536
__device__ __nv_bfloat16 g_kvb[(size_t)ROWS*2*D];      // mha2 [K|V], ld 1024
__device__ __nv_bfloat16 g_ctxb[ROWS*D];
__device__ __nv_bfloat16 g_hidb[(size_t)2*ROWS*2*D];
__device__ __nv_bfloat16 g_xlnb[(size_t)2*ROWS*D];
__device__ __nv_bfloat16 g_wb[(size_t)12*DD];
__device__ float g_bias_kq[3*D];                       // [bin1(k|v) | bin2(q)]
__device__ float g_proj[ROWS*D];
__device__ float g_ffn[(size_t)2*ROWS*D];

// weight layout in g_wb: [win1 (3DD) | win2 (3DD) | wout1 | wout2 | fw1 | fw2]
#define WB_W1Q  0            /* win1 q        */
#define WB_KVQ  (DD)         /* [W1kv | W2q]  : 3DD contiguous */
#define WB_W2KV (4*DD)
#define WB_WO1  (6*DD)
#define WB_WO2  (7*DD)
#define WB_F1   (8*DD)
#define WB_F2   (10*DD)

// ======================= helpers =======================
__device__ __forceinline__ uint32_t smem_u32(const void* p) {
  uint32_t a;
  asm("{ .reg .u64 t; cvta.to.shared.u64 t, %1; cvt.u32.u64 %0, t; }"
      : "=r"(a) : "l"(p));
  return a;
}

#define CP_ASYNC16(dst, src) \
  asm volatile("cp.async.cg.shared.global [%0], [%1], 16;" \
               :: "r"(dst), "l"(src))
#define CP_COMMIT() asm volatile("cp.async.commit_group;")
#define CP_WAIT(n)  asm volatile("cp.async.wait_group %0;" :: "n"(n))

#define LDSM_X4(r0, r1, r2, r3, addr) \
  asm volatile("ldmatrix.sync.aligned.m8n8.x4.shared.b16 {%0,%1,%2,%3}, [%4];" \
               : "=r"(r0), "=r"(r1), "=r"(r2), "=r"(r3) : "r"(addr))
#define LDSM_X4_T(r0, r1, r2, r3, addr) \
  asm volatile("ldmatrix.sync.aligned.m8n8.x4.trans.shared.b16 {%0,%1,%2,%3}, [%4];" \
               : "=r"(r0), "=r"(r1), "=r"(r2), "=r"(r3) : "r"(addr))

#define MMA_BF16(c, a, b) \
  asm volatile( \
    "mma.sync.aligned.m16n8k16.row.col.f32.bf16.bf16.f32 " \
    "{%0,%1,%2,%3}, {%4,%5,%6,%7}, {%8,%9}, {%0,%1,%2,%3};" \
    : "+f"((c)[0]), "+f"((c)[1]), "+f"((c)[2]), "+f"((c)[3]) \
    : "r"((a)[0]), "r"((a)[1]), "r"((a)[2]), "r"((a)[3]), \
      "r"((b)[0]), "r"((b)[1]))

__device__ __forceinline__ void stcs_f2(float* p, float2 v) {
  asm volatile("st.global.cs.v2.f32 [%0], {%1, %2};" :: "l"(p), "f"(v.x), "f"(v.y));
}

// ---------------- all fp32 -> bf16 converts + bias concat, ONE launch -----
#define CV_Q4    (ROWS*D/4)
#define CV_C3    (3*DD/4)
#define CV_C1    (DD/4)
#define CV_C2    (2*DD/4)
#define CV_WTOT  (12*DD/4)
#define CV_TOT   (2*CV_Q4 + CV_WTOT + 1024)   /* 1024-slot tail for bias */
#define CV_BLOCKS (CV_TOT/256)

__global__ void __launch_bounds__(256) convert_all(
    const float* __restrict__ x1, const float* __restrict__ x2,
    const float* __restrict__ win1, const float* __restrict__ win2,
    const float* __restrict__ wout1, const float* __restrict__ wout2,
    const float* __restrict__ fw1, const float* __restrict__ fw2,
    const float* __restrict__ bin1, const float* __restrict__ bin2,
    __nv_bfloat16* __restrict__ x1b, __nv_bfloat16* __restrict__ x2b,
    __nv_bfloat16* __restrict__ wb, float* __restrict__ bias_kq)
{
  long i = (long)blockIdx.x * 256 + threadIdx.x;
  if (i >= 2 * CV_Q4 + CV_WTOT) {
    long u = i - (2 * CV_Q4 + CV_WTOT);
    if (u < 3 * D / 4) {   // 384 float4s: [bin1[D:3D) | bin2[0:D)]
      float4 v = (u < 2 * D / 4) ? ((const float4*)(bin1 + D))[u]
                                 : ((const float4*)bin2)[u - 2 * D / 4];
      ((float4*)bias_kq)[u] = v;
    }
    return;
  }
  const float* src;
  __nv_bfloat16* dstb;
  long off, sidx;
  if (i < CV_Q4) { src = x1; dstb = x1b; off = i; sidx = i; }
  else if (i < 2 * CV_Q4) { src = x2; dstb = x2b; off = i - CV_Q4; sidx = off; }
  else {
    long w = i - 2 * CV_Q4;
    dstb = wb; sidx = w;
    if      (w < CV_C3)                  { src = win1;  off = w; }
    else if (w < 2*CV_C3)                { src = win2;  off = w - CV_C3; }
    else if (w < 2*CV_C3 + CV_C1)        { src = wout1; off = w - 2*CV_C3; }
    else if (w < 2*CV_C3 + 2*CV_C1)      { src = wout2; off = w - (2*CV_C3 + CV_C1); }
    else if (w < 2*CV_C3 + 2*CV_C1 + CV_C2) { src = fw1; off = w - (2*CV_C3 + 2*CV_C1); }
    else                                 { src = fw2;  off = w - (2*CV_C3 + 2*CV_C1 + CV_C2); }
  }
  float4 v = ((const float4*)src)[off];
  __nv_bfloat162 a = __floats2bfloat162_rn(v.x, v.y);
  __nv_bfloat162 b = __floats2bfloat162_rn(v.z, v.w);
  ((uint2*)dstb)[sidx] = make_uint2(*(uint32_t*)&a, *(uint32_t*)&b);
}

// ======================= bf16 GEMM (R6 config) =============================
__global__ void __launch_bounds__(256) gemm_bf16(
    const __nv_bfloat16* __restrict__ A, const __nv_bfloat16* __restrict__ B,
    const float* __restrict__ bias, float* __restrict__ Cf,
    __nv_bfloat16* __restrict__ Cb,
    int nslab, int lda, int ldb, int ldc, int relu)
{
  __shared__ __align__(16) __nv_bfloat16 As[4][128][40];
  __shared__ __align__(16) __nv_bfloat16 Bs[4][128][40];

  const int tid = threadIdx.x;
  const int wid = tid >> 5, l = tid & 31;
  const int warp_m = wid & 3, warp_n = wid >> 2;

  const int bm = blockIdx.y * 128;
  const int bn = blockIdx.x * 128;

  float acc[2][8][4];
  #pragma unroll
  for (int i = 0; i < 2; i++)
    #pragma unroll
    for (int j = 0; j < 8; j++)
      #pragma unroll
      for (int k = 0; k < 4; k++) acc[i][j][k] = 0.f;

  auto issue = [&](int slab, int stg) {
    const int k0 = slab << 5;
    #pragma unroll
    for (int it = 0; it < 2; ++it) {
      int idx = tid + it * 256;
      int r = idx >> 2, c = (idx & 3) << 3;
      CP_ASYNC16(smem_u32(&As[stg][r][c]),
                 A + (size_t)(bm + r) * lda + k0 + c);
    }
    #pragma unroll
    for (int it = 0; it < 2; ++it) {
      int idx = tid + it * 256;
      int r = idx >> 2, c = (idx & 3) << 3;
      CP_ASYNC16(smem_u32(&Bs[stg][r][c]),
                 B + (size_t)(bn + r) * ldb + k0 + c);
    }
    CP_COMMIT();
  };

  #pragma unroll
  for (int s = 0; s < 3; s++) {
    if (s < nslab) issue(s, s); else CP_COMMIT();
  }

  for (int i = 0; i < nslab; i++) {
    CP_WAIT(2);
    __syncthreads();
    const int buf = i & 3;
    if (i + 3 < nslab) issue(i + 3, (i + 3) & 3); else CP_COMMIT();

    const uint32_t a_base = smem_u32(&As[buf][0][0]);
    const uint32_t b_base = smem_u32(&Bs[buf][0][0]);
    #pragma unroll
    for (int ks = 0; ks < 2; ks++) {
      const int k0 = ks * 16;
      uint32_t afr[2][4];
      #pragma unroll
      for (int mf = 0; mf < 2; mf++) {
        int row = warp_m * 32 + mf * 16 + (l & 15);
        uint32_t addr = a_base + (uint32_t)(row * 80 + (k0 + ((l >> 4) << 3)) * 2);
        LDSM_X4(afr[mf][0], afr[mf][1], afr[mf][2], afr[mf][3], addr);
      }
      uint32_t bfr[8][2];
      #pragma unroll
      for (int nf = 0; nf < 8; nf += 2) {
        int row = warp_n * 64 + nf * 8 + ((l >> 4) << 3) + (l & 7);
        int col = k0 + ((l >> 3) & 1) * 8;
        uint32_t addr = b_base + (uint32_t)(row * 80 + col * 2);
        LDSM_X4(bfr[nf][0], bfr[nf][1], bfr[nf + 1][0], bfr[nf + 1][1], addr);
      }
      #pragma unroll
      for (int mf = 0; mf < 2; mf++)
        #pragma unroll
        for (int nf = 0; nf < 8; nf++)
          MMA_BF16(acc[mf][nf], afr[mf], bfr[nf]);
    }
  }

  const int gid = l >> 2, tig = l & 3;
  #pragma unroll
  for (int mf = 0; mf < 2; mf++) {
    const int row = bm + warp_m * 32 + mf * 16 + gid;
    #pragma unroll
    for (int nf = 0; nf < 8; nf++) {
      const int col = bn + warp_n * 64 + nf * 8 + tig * 2;
      float2 bv = make_float2(0.f, 0.f);
      if (bias) bv = *(const float2*)(bias + col);
      float2 v0, v1;
      v0.x = acc[mf][nf][0] + bv.x;
      v0.y = acc[mf][nf][1] + bv.y;
      v1.x = acc[mf][nf][2] + bv.x;
      v1.y = acc[mf][nf][3] + bv.y;
      if (relu) {
        v0.x = fmaxf(v0.x, 0.f); v0.y = fmaxf(v0.y, 0.f);
        v1.x = fmaxf(v1.x, 0.f); v1.y = fmaxf(v1.y, 0.f);
      }
      if (Cf) {
        *(float2*)(Cf + (size_t)row * ldc + col) = v0;
        *(float2*)(Cf + (size_t)(row + 8) * ldc + col) = v1;
      }
      if (Cb) {
        __nv_bfloat162 h0 = __floats2bfloat162_rn(v0.x, v0.y);
        __nv_bfloat162 h1 = __floats2bfloat162_rn(v1.x, v1.y);
        *(uint32_t*)(Cb + (size_t)row * ldc + col) = *(uint32_t*)&h0;
        *(uint32_t*)(Cb + (size_t)(row + 8) * ldc + col) = *(uint32_t*)&h1;
      }
    }
  }
}

// ======================= fused attention (strided Q/KV) ====================
#define FA_QS   0
#define FA_KS   18432
#define FA_VS   55296
#define FA_ZS   73728
#define FA_SMEM 74240
#define FA_KSTRIDE 18432

__global__ void __launch_bounds__(256, 2) fused_attn(
    const __nv_bfloat16* __restrict__ Q, int qld,
    const __nv_bfloat16* __restrict__ KV, int kvld,
    float* __restrict__ attn, __nv_bfloat16* __restrict__ ctxb)
{
  extern __shared__ char sm[];
  float* Zs = (float*)(sm + FA_ZS);

  const int tid = threadIdx.x;
  const int wid = tid >> 5, l = tid & 31;
  const int gid = l >> 2, tig = l & 3;

  const int z = blockIdx.y;
  const int b = z >> 3, h = z & 7;
  const int l0 = blockIdx.x * 128;

  const __nv_bfloat16* Qg = Q  + (size_t)b * LSEQ * qld + h * HD;
  const __nv_bfloat16* Kg = KV + (size_t)b * LSEQ * kvld + h * HD;
  const __nv_bfloat16* Vg = Kg + D;
  float* Pg = attn + (size_t)z * LSEQ * LSEQ;
  __nv_bfloat16* Ogb = ctxb + (size_t)b * LSEQ * D + h * HD;

  const uint32_t qsb = smem_u32(sm + FA_QS);
  const uint32_t ks0 = smem_u32(sm + FA_KS);
  const uint32_t vsb = smem_u32(sm + FA_VS);

  auto issue_q = [&]() {
    #pragma unroll
    for (int it = 0; it < 4; ++it) {
      int idx = tid + it * 256;
      int r = idx >> 3, c = (idx & 7) << 3;
      CP_ASYNC16(qsb + (uint32_t)(r * 144 + c * 2),
                 Qg + (size_t)(l0 + r) * qld + c);
    }
    CP_COMMIT();
  };
  auto issue_k = [&](int s0, int kb) {
    const uint32_t base = ks0 + kb * FA_KSTRIDE;
    #pragma unroll
    for (int it = 0; it < 4; ++it) {
      int idx = tid + it * 256;
      int r = idx >> 3, c = (idx & 7) << 3;
      CP_ASYNC16(base + (uint32_t)(r * 144 + c * 2),
                 Kg + (size_t)(s0 + r) * kvld + c);
    }
    CP_COMMIT();
  };
  auto issue_v = [&](int s0) {
    #pragma unroll
    for (int it = 0; it < 4; ++it) {
      int idx = tid + it * 256;
      int r = idx >> 3, c = (idx & 7) << 3;
      CP_ASYNC16(vsb + (uint32_t)(r * 144 + c * 2),
                 Vg + (size_t)(s0 + r) * kvld + c);
    }
    CP_COMMIT();
  };

  issue_q();
  issue_k(0, 0);

  auto s_half = [&](float (*acc)[4], int kb, int half) {
    const uint32_t ksb = ks0 + kb * FA_KSTRIDE;
    #pragma unroll
    for (int j = 0; j < 8; j++)
      #pragma unroll
      for (int k = 0; k < 4; k++) acc[j][k] = 0.f;
    #pragma unroll
    for (int ks = 0; ks < 4; ks++) {
      const int k0 = ks * 16;
      uint32_t afr[4];
      {
        int row = wid * 16 + (l & 15);
        uint32_t addr = qsb + (uint32_t)(row * 144 + (k0 + ((l >> 4) << 3)) * 2);
        LDSM_X4(afr[0], afr[1], afr[2], afr[3], addr);
      }
      uint32_t bfr[8][2];
      #pragma unroll
      for (int nf = 0; nf < 8; nf += 2) {
        int row = half * 64 + nf * 8 + ((l >> 4) << 3) + (l & 7);
        int col = k0 + ((l >> 3) & 1) * 8;
        uint32_t addr = ksb + (uint32_t)(row * 144 + col * 2);
        LDSM_X4(bfr[nf][0], bfr[nf][1], bfr[nf + 1][0], bfr[nf + 1][1], addr);
      }
      #pragma unroll
      for (int nf = 0; nf < 8; nf++)
        MMA_BF16(acc[nf], afr, bfr[nf]);
    }
  };

  // pass 1: row sums
  {
    float zr[2] = {0.f, 0.f};
    for (int st = 0; st < 8; st++) {
      const int kb = st & 1;
      CP_WAIT(0);
      __syncthreads();
      if (st < 7) issue_k((st + 1) * 128, kb ^ 1); else CP_COMMIT();
      #pragma unroll
      for (int half = 0; half < 2; half++) {
        float acc[8][4];
        s_half(acc, kb, half);
        #pragma unroll
        for (int nf = 0; nf < 8; nf++) {
          zr[0] += __expf(acc[nf][0] * 0.125f) + __expf(acc[nf][1] * 0.125f);
          zr[1] += __expf(acc[nf][2] * 0.125f) + __expf(acc[nf][3] * 0.125f);
        }
      }
    }
    #pragma unroll
    for (int rp = 0; rp < 2; rp++) {
      float v = zr[rp];
      v += __shfl_xor_sync(0xffffffffu, v, 1);
      v += __shfl_xor_sync(0xffffffffu, v, 2);
      if (tig == 0) Zs[wid * 16 + rp * 8 + gid] = v;
    }
    __syncthreads();
    if (tid < 128) Zs[tid] = 1.f / Zs[tid];
    issue_k(0, 0);
    issue_v(0);
    __syncthreads();
  }

  float iz[2];
  iz[0] = Zs[wid * 16 + gid];
  iz[1] = Zs[wid * 16 + 8 + gid];

  // pass 2: write P (streaming), accumulate O = P@V
  float oacc[8][4];
  #pragma unroll
  for (int j = 0; j < 8; j++)
    #pragma unroll
    for (int k = 0; k < 4; k++) oacc[j][k] = 0.f;

  for (int st = 0; st < 8; st++) {
    const int s0 = st * 128;
    const int kb = st & 1;
    CP_WAIT(1);
    __syncthreads();
    if (st < 7) issue_k(s0 + 128, kb ^ 1); else CP_COMMIT();

    uint32_t pk[8][4];
    #pragma unroll
    for (int half = 0; half < 2; half++) {
      float acc[8][4];
      s_half(acc, kb, half);
      #pragma unroll
      for (int nf = 0; nf < 8; nf++) {
        const int gnf = half * 8 + nf;
        const int c = gnf * 8 + tig * 2;
        const int r0 = wid * 16 + gid;
        float p00 = __expf(acc[nf][0] * 0.125f) * iz[0];
        float p01 = __expf(acc[nf][1] * 0.125f) * iz[0];
        float p10 = __expf(acc[nf][2] * 0.125f) * iz[1];
        float p11 = __expf(acc[nf][3] * 0.125f) * iz[1];
        stcs_f2(Pg + (size_t)(l0 + r0) * LSEQ + s0 + c, make_float2(p00, p01));
        stcs_f2(Pg + (size_t)(l0 + r0 + 8) * LSEQ + s0 + c, make_float2(p10, p11));
        __nv_bfloat162 q0 = __floats2bfloat162_rn(p00, p01);
        __nv_bfloat162 q1 = __floats2bfloat162_rn(p10, p11);
        const int kk = gnf >> 1;
        if ((gnf & 1) == 0) {
          pk[kk][0] = *(uint32_t*)&q0;
          pk[kk][1] = *(uint32_t*)&q1;
        } else {
          pk[kk][2] = *(uint32_t*)&q0;
          pk[kk][3] = *(uint32_t*)&q1;
        }
      }
    }
    CP_WAIT(1);
    __syncthreads();

    #pragma unroll
    for (int kk = 0; kk < 8; kk++) {
      uint32_t bfr[8][2];
      #pragma unroll
      for (int nf = 0; nf < 8; nf += 2) {
        int krow = kk * 16 + ((l >> 3) & 1) * 8 + (l & 7);
        int ncol = nf * 8 + ((l >> 4) << 3);
        uint32_t addr = vsb + (uint32_t)(krow * 144 + ncol * 2);
        LDSM_X4_T(bfr[nf][0], bfr[nf][1], bfr[nf + 1][0], bfr[nf + 1][1], addr);
      }
      #pragma unroll
      for (int nf = 0; nf < 8; nf++)
        MMA_BF16(oacc[nf], pk[kk], bfr[nf]);
    }
    __syncthreads();
    if (st < 7) issue_v(s0 + 128); else CP_COMMIT();
  }
  CP_WAIT(0);

  {
    const int r0 = l0 + wid * 16 + gid;
    #pragma unroll
    for (int nf = 0; nf < 8; nf++) {
      const int c = nf * 8 + tig * 2;
      __nv_bfloat162 h0 = __floats2bfloat162_rn(oacc[nf][0], oacc[nf][1]);
      __nv_bfloat162 h1 = __floats2bfloat162_rn(oacc[nf][2], oacc[nf][3]);
      *(uint32_t*)(Ogb + (size_t)r0 * D + c) = *(uint32_t*)&h0;
      *(uint32_t*)(Ogb + (size_t)(r0 + 8) * D + c) = *(uint32_t*)&h1;
    }
  }
}

// ---------------- out = LN(x + y) * g + b, rows of 512 ----------------
__global__ void __launch_bounds__(256) residual_ln_kernel(
    const float* __restrict__ x, const float* __restrict__ y,
    const float* __restrict__ g, const float* __restrict__ b,
    float* __restrict__ out, __nv_bfloat16* __restrict__ outb)
{
  __shared__ float shs[8], shq[8];
  const size_t row = blockIdx.x;
  const int t = threadIdx.x;
  float2 xa = ((const float2*)x)[row * 256 + t];
  float2 ya = ((const float2*)y)[row * 256 + t];
  float v0 = xa.x + ya.x, v1 = xa.y + ya.y;
  float s = v0 + v1, q = v0*v0 + v1*v1;
  #pragma unroll
  for (int o = 16; o > 0; o >>= 1) {
    s += __shfl_xor_sync(0xffffffffu, s, o);
    q += __shfl_xor_sync(0xffffffffu, q, o);
  }
  if ((t & 31) == 0) { shs[t >> 5] = s; shq[t >> 5] = q; }
  __syncthreads();
  s = 0.f; q = 0.f;
  #pragma unroll
  for (int i = 0; i < 8; i++) { s += shs[i]; q += shq[i]; }
  float mu  = s * (1.f / 512.f);
  float var = q * (1.f / 512.f) - mu * mu;
  float inv = rsqrtf(var + 1e-5f);
  float2 gg = ((const float2*)g)[t];
  float2 bb = ((const float2*)b)[t];
  float2 o2;
  o2.x = (v0 - mu) * inv * gg.x + bb.x;
  o2.y = (v1 - mu) * inv * gg.y + bb.y;
  ((float2*)out)[row * 256 + t] = o2;
  if (outb) {
    __nv_bfloat162 h = __floats2bfloat162_rn(o2.x, o2.y);
    ((uint32_t*)outb)[row * 256 + t] = *(uint32_t*)&h;
  }
}

// ---------------- host-side orchestration ----------------
extern "C" void kernel_launch(void* const* d_in, const int* in_sizes, int n_in,
                              void* d_out, int out_size)
{
  const float* x1    = (const float*)d_in[0];
  const float* x2    = (const float*)d_in[1];
  const float* win1  = (const float*)d_in[2];
  const float* bin1  = (const float*)d_in[3];
  const float* wout1 = (const float*)d_in[4];
  const float* bout1 = (const float*)d_in[5];
  const float* win2  = (const float*)d_in[6];
  const float* bin2  = (const float*)d_in[7];
  const float* wout2 = (const float*)d_in[8];
  const float* bout2 = (const float*)d_in[9];
  const float* g1    = (const float*)d_in[10];
  const float* b1    = (const float*)d_in[11];
  const float* g2    = (const float*)d_in[12];
  const float* b2    = (const float*)d_in[13];
  const float* fw1   = (const float*)d_in[14];
  const float* fb1   = (const float*)d_in[15];
  const float* fw2   = (const float*)d_in[16];
  const float* fb2   = (const float*)d_in[17];
  const float* g3    = (const float*)d_in[18];
  const float* b3    = (const float*)d_in[19];

  cudaFuncSetAttribute(fused_attn, cudaFuncAttributeMaxDynamicSharedMemorySize, FA_SMEM);

  // side stream + events, created once; fall back to serial if creation fails
  static cudaStream_t s1 = nullptr;
  static cudaEvent_t ev_fork = nullptr, ev_join = nullptr;
  static int stream_ok = -1;
  if (stream_ok < 0) {
    stream_ok = 1;
    if (cudaStreamCreateWithFlags(&s1, cudaStreamNonBlocking) != cudaSuccess) stream_ok = 0;
    if (stream_ok && cudaEventCreateWithFlags(&ev_fork, cudaEventDisableTiming) != cudaSuccess) stream_ok = 0;
    if (stream_ok && cudaEventCreateWithFlags(&ev_join, cudaEventDisableTiming) != cudaSuccess) stream_ok = 0;
  }
  cudaStream_t br = stream_ok ? s1 : 0;

  float* out = (float*)d_out;
  float* ox1 = out;
  float* ox2 = out + (size_t)ROWS * D;
  float* w12 = out + (size_t)2 * ROWS * D;
  float* w21 = w12 + (size_t)BH * LSEQ * LSEQ;

  __nv_bfloat16 *x1b, *x2b, *qb, *kq, *kvb, *ctxb, *hidb, *xlnb, *wb;
  float *proj, *ffn, *bias_kq;
  cudaGetSymbolAddress((void**)&x1b,  g_x1b);
  cudaGetSymbolAddress((void**)&x2b,  g_x2b);
  cudaGetSymbolAddress((void**)&qb,   g_qb);
  cudaGetSymbolAddress((void**)&kq,   g_kq);
  cudaGetSymbolAddress((void**)&kvb,  g_kvb);
  cudaGetSymbolAddress((void**)&ctxb, g_ctxb);
  cudaGetSymbolAddress((void**)&hidb, g_hidb);
  cudaGetSymbolAddress((void**)&xlnb, g_xlnb);
  cudaGetSymbolAddress((void**)&wb,   g_wb);
  cudaGetSymbolAddress((void**)&proj, g_proj);
  cudaGetSymbolAddress((void**)&ffn,  g_ffn);
  cudaGetSymbolAddress((void**)&bias_kq, g_bias_kq);

  __nv_bfloat16* qb2   = kq + 2 * D;                    // Q2 cols in kq, ld 3D
  __nv_bfloat16* xlnb2 = xlnb + (size_t)ROWS * D;
  __nv_bfloat16* hidb1 = hidb;
  __nv_bfloat16* hidb2 = hidb + (size_t)ROWS * 2 * D;
  float* ffn1 = ffn;
  float* ffn2 = ffn + (size_t)ROWS * D;

  // ---------------- mha1 (+ Q2 merged into KV1 projection) ----------------
  convert_all<<<CV_BLOCKS, 256>>>(x1, x2, win1, win2, wout1, wout2,          // 0
                                  fw1, fw2, bin1, bin2, x1b, x2b, wb, bias_kq);
  gemm_bf16<<<dim3(4, 64), 256>>>(x1b, wb + WB_W1Q, bin1, nullptr, qb,       // 1
                                  16, D, D, D, 0);
  gemm_bf16<<<dim3(12, 64), 256>>>(x2b, wb + WB_KVQ, bias_kq, nullptr, kq,   // 2
                                   16, D, D, 3*D, 0);
  fused_attn<<<dim3(8, BH), 256, FA_SMEM>>>(qb, D, kq, 3*D, w12, ctxb);      // 3
  gemm_bf16<<<dim3(4, 64), 256>>>(ctxb, wb + WB_WO1, bout1, proj, nullptr,   // 4
                                  16, D, D, D, 0);
  residual_ln_kernel<<<ROWS, 256>>>(x1, proj, g1, b1, ox1, xlnb);            // 5

  // ---------------- fork: x1-FFN chain on side stream ----------------
  if (stream_ok) {
    cudaEventRecord(ev_fork, 0);
    cudaStreamWaitEvent(s1, ev_fork, 0);
  }
  gemm_bf16<<<dim3(8, 64), 256, 0, br>>>(xlnb, wb + WB_F1, fb1, nullptr,     // br
                                         hidb1, 16, D, D, 2*D, 1);
  gemm_bf16<<<dim3(4, 64), 256, 0, br>>>(hidb1, wb + WB_F2, fb2, ffn1,       // br
                                         nullptr, 32, 2*D, 2*D, D, 0);
  residual_ln_kernel<<<ROWS, 256, 0, br>>>(ox1, ffn1, g3, b3, ox1, nullptr); // br
  if (stream_ok) cudaEventRecord(ev_join, s1);

  // ---------------- main: mha2 + x2-FFN ----------------
  gemm_bf16<<<dim3(8, 64), 256>>>(xlnb, wb + WB_W2KV, bin2 + D,              //
                                  nullptr, kvb, 16, D, D, 2*D, 0);
  fused_attn<<<dim3(8, BH), 256, FA_SMEM>>>(qb2, 3*D, kvb, 2*D, w21, ctxb);  //
  gemm_bf16<<<dim3(4, 64), 256>>>(ctxb, wb + WB_WO2, bout2, proj, nullptr,   //
                                  16, D, D, D, 0);
  residual_ln_kernel<<<ROWS, 256>>>(x2, proj, g2, b2, ox2, xlnb2);           //
  gemm_bf16<<<dim3(8, 64), 256>>>(xlnb2, wb + WB_F1, fb1, nullptr, hidb2,    //
                                  16, D, D, 2*D, 1);
  gemm_bf16<<<dim3(4, 64), 256>>>(hidb2, wb + WB_F2, fb2, ffn2, nullptr,     //
                                  32, 2*D, 2*D, D, 0);
  residual_ln_kernel<<<ROWS, 256>>>(ox2, ffn2, g3, b3, ox2, nullptr);        //

  // ---------------- join ----------------
  if (stream_ok) cudaStreamWaitEvent(0, ev_join, 0);
}